// round 14
// baseline (speedup 1.0000x reference)
#include <cuda_runtime.h>
#include <cuda_fp16.h>
#include <cstdint>

// Problem constants
#define NN 50000
#define DD 256
#define RR 16
#define BB 8
#define NCOL 2304               // 8 basis blocks + root = 9 * 256
#define KK 256                  // pure fp16 single-product GEMM
#define EE 800000
#define LN_EPS 1e-5f
#define NBANDS 391

// ---- static scratch ----
__device__ __half g_Ap[(size_t)NN * KK];     // fp16 activations [N,256]
__device__ __half g_Bp1[(size_t)NCOL * KK];  // fp16 weights layer 1
__device__ __half g_Bp2[(size_t)NCOL * KK];  // fp16 weights layer 2
__device__ __half g_Y[(size_t)NN * NCOL];    // x @ W  [N,2304] fp16
__device__ __half g_H[(size_t)NN * RR * DD]; // per-relation fp16
__device__ float g_x1[(size_t)NN * DD];      // layer-1 output
__device__ int g_bc1[512];                   // band counters layer 1
__device__ int g_bc2[512];                   // band counters layer 2
// CSR over dst
__device__ int g_deg[NN];
__device__ int g_rowptr[NN];
__device__ int g_bsum[256];
__device__ int g_fill[NN];
__device__ uint32_t g_epack[EE];             // src | (et << 16)
__device__ float g_ew[EE];

static __device__ __forceinline__ uint32_t s2u(const void* p) {
    uint32_t a;
    asm("{ .reg .u64 t; cvta.to.shared.u64 t, %1; cvt.u32.u64 %0, t; }" : "=r"(a) : "l"(p));
    return a;
}
#define CP_COMMIT() asm volatile("cp.async.commit_group;" ::: "memory")
#define CP_WAIT(n)  asm volatile("cp.async.wait_group %0;" :: "n"(n) : "memory")
#define LDSM4(r, addr) \
    asm volatile("ldmatrix.sync.aligned.m8n8.x4.shared.b16 {%0,%1,%2,%3}, [%4];" \
        : "=r"((r)[0]), "=r"((r)[1]), "=r"((r)[2]), "=r"((r)[3]) : "r"(addr))

// ===========================================================================
// CSR build
__global__ void k_zero_degfill(int M) {
    int t = blockIdx.x * 256 + threadIdx.x;
    if (t < M) { g_deg[t] = 0; g_fill[t] = 0; }
    if (t < 512) { g_bc1[t] = 0; g_bc2[t] = 0; }
}
__global__ void k_deg_count(const int* __restrict__ ei, int E) {
    int t = blockIdx.x * 256 + threadIdx.x;
    if (t < E) atomicAdd(&g_deg[ei[E + t]], 1);
}
__global__ void k_scan1(int M) {
    __shared__ int s[256];
    int i = blockIdx.x * 256 + threadIdx.x;
    int v = (i < M) ? g_deg[i] : 0;
    s[threadIdx.x] = v;
    __syncthreads();
    for (int off = 1; off < 256; off <<= 1) {
        int t = (threadIdx.x >= off) ? s[threadIdx.x - off] : 0;
        __syncthreads();
        s[threadIdx.x] += t;
        __syncthreads();
    }
    if (i < M) g_rowptr[i] = s[threadIdx.x] - v;
    if (threadIdx.x == 255) g_bsum[blockIdx.x] = s[255];
}
__global__ void k_scan2(int nb) {
    __shared__ int s[256];
    int v = (threadIdx.x < nb) ? g_bsum[threadIdx.x] : 0;
    s[threadIdx.x] = v;
    __syncthreads();
    for (int off = 1; off < 256; off <<= 1) {
        int t = (threadIdx.x >= off) ? s[threadIdx.x - off] : 0;
        __syncthreads();
        s[threadIdx.x] += t;
        __syncthreads();
    }
    g_bsum[threadIdx.x] = s[threadIdx.x] - v;
}
__global__ void k_scan3(int M) {
    int i = blockIdx.x * 256 + threadIdx.x;
    if (i < M) g_rowptr[i] += g_bsum[i >> 8];
}
__global__ void k_fill(const int* __restrict__ ei, const int* __restrict__ et,
                       const float* __restrict__ ea, int E) {
    int t = blockIdx.x * 256 + threadIdx.x;
    if (t >= E) return;
    int dst = ei[E + t];
    int slot = atomicAdd(&g_fill[dst], 1);
    int idx = g_rowptr[dst] + slot;
    g_epack[idx] = (uint32_t)ei[t] | ((uint32_t)et[t] << 16);
    g_ew[idx] = ea[t];
}

// ===========================================================================
// Prep: fp16 weights into the given buffer (both layers prepped upfront)
__global__ void k_prepw(const float* __restrict__ basis, const float* __restrict__ root,
                        __half* __restrict__ Bp) {
    int c = blockIdx.x;      // 0..2303
    int k = threadIdx.x;     // 0..255
    float w;
    if (c < BB * DD) {
        int b = c >> 8, o = c & 255;
        w = basis[((size_t)b * DD + k) * DD + o];
    } else {
        w = root[(size_t)k * DD + (c - BB * DD)];
    }
    Bp[(size_t)c * KK + k] = __float2half_rn(w);
}
__global__ void k_cvt_x(const float* __restrict__ x, int M) {
    int t = blockIdx.x * 256 + threadIdx.x;
    if (t >= M * DD) return;
    g_Ap[t] = __float2half_rn(x[t]);
}

// ===========================================================================
// fp16 mma.sync GEMM with band-counter fused expand.
// After the Y epilogue, the last TWO CTAs finishing a 128-row band each expand
// 64 rows of that band (H[n,r,:] = sum_b att[r,b]*Y[n,b*256+:]), reading Y
// from L2 and overlapping with other CTAs' tensor work.
#define BK 64
#define TILE_B 18432
#define SMEM_TOTAL (4 * TILE_B + 1024)   // buffers + packed att (128 x f32x2)

static __device__ __forceinline__ void mma16816(float* c, const uint32_t* a,
                                                const uint32_t* b) {
    asm volatile(
        "mma.sync.aligned.m16n8k16.row.col.f32.f16.f16.f32 "
        "{%0,%1,%2,%3}, {%4,%5,%6,%7}, {%8,%9}, {%0,%1,%2,%3};\n"
        : "+f"(c[0]), "+f"(c[1]), "+f"(c[2]), "+f"(c[3])
        : "r"(a[0]), "r"(a[1]), "r"(a[2]), "r"(a[3]), "r"(b[0]), "r"(b[1]));
}

__global__ __launch_bounds__(256, 2) void k_gemm_mma(int M, const __half* __restrict__ Bp,
                                                     int* __restrict__ bandcnt,
                                                     const float* __restrict__ att) {
    extern __shared__ char smem[];
    const uint32_t sbase = s2u(smem);
    const int tid = threadIdx.x;
    const int wid = tid >> 5, lane = tid & 31;
    const int r4 = lane >> 2, q = lane & 3;
    const int rowBase = blockIdx.y * 128;
    const int colBase = blockIdx.x * 128;
    const int wm = (wid >> 2) * 64;
    const int wn = (wid & 3) * 32;

    // packed att into tail smem
    unsigned long long* sap = (unsigned long long*)(smem + 4 * TILE_B);
    if (tid < RR * BB) {
        float v = att[tid];
        unsigned long long pk;
        asm("mov.b64 %0, {%1, %2};" : "=l"(pk) : "f"(v), "f"(v));
        sap[tid] = pk;
    }

    float acc[4][4][4];
#pragma unroll
    for (int i = 0; i < 4; i++)
#pragma unroll
        for (int j = 0; j < 4; j++)
#pragma unroll
            for (int t = 0; t < 4; t++) acc[i][j][t] = 0.f;

    uint32_t aOff[4];
#pragma unroll
    for (int mi = 0; mi < 4; mi++)
        aOff[mi] = (uint32_t)((wm + mi * 16 + (lane & 15)) * 144 + ((lane >> 4) & 1) * 16);
    uint32_t bOff[2];
#pragma unroll
    for (int p = 0; p < 2; p++)
        bOff[p] = (uint32_t)((wn + p * 16 + ((lane & 16) >> 1) + (lane & 7)) * 144
                             + ((lane >> 3) & 1) * 16);

    auto issueTiles = [&](int kt, int buf) {
        int k0 = kt * BK;
        uint32_t sa = sbase + buf * TILE_B;
        uint32_t sb = sbase + 2 * TILE_B + buf * TILE_B;
#pragma unroll
        for (int i = 0; i < 4; i++) {
            int e = tid + i * 256;
            int r = e >> 3, c8 = e & 7;
            int gr = rowBase + r;
            uint32_t sz = (gr < M) ? 16u : 0u;
            const void* src = &g_Ap[(size_t)(gr < M ? gr : 0) * KK + k0 + c8 * 8];
            asm volatile("cp.async.cg.shared.global [%0], [%1], 16, %2;"
                         :: "r"(sa + r * 144 + c8 * 16), "l"(src), "r"(sz));
        }
#pragma unroll
        for (int i = 0; i < 4; i++) {
            int e = tid + i * 256;
            int r = e >> 3, c8 = e & 7;
            const void* src = &Bp[(size_t)(colBase + r) * KK + k0 + c8 * 8];
            asm volatile("cp.async.cg.shared.global [%0], [%1], 16;"
                         :: "r"(sb + r * 144 + c8 * 16), "l"(src));
        }
    };

    const int NT = KK / BK;   // 4
    issueTiles(0, 0);
    CP_COMMIT();

    for (int kt = 0; kt < NT; kt++) {
        int buf = kt & 1;
        if (kt + 1 < NT) {
            issueTiles(kt + 1, buf ^ 1);
            CP_COMMIT();
            CP_WAIT(1);
        } else {
            CP_WAIT(0);
        }
        __syncthreads();

        uint32_t sa = sbase + buf * TILE_B;
        uint32_t sb = sbase + 2 * TILE_B + buf * TILE_B;
#pragma unroll
        for (int ks = 0; ks < 4; ks++) {
            uint32_t af[4][4], bf[2][4];
#pragma unroll
            for (int mi = 0; mi < 4; mi++) LDSM4(af[mi], sa + aOff[mi] + ks * 32);
#pragma unroll
            for (int p = 0; p < 2; p++)    LDSM4(bf[p], sb + bOff[p] + ks * 32);
#pragma unroll
            for (int mi = 0; mi < 4; mi++)
#pragma unroll
                for (int ni = 0; ni < 4; ni++)
                    mma16816(acc[mi][ni], af[mi], &bf[ni >> 1][(ni & 1) * 2]);
        }
        __syncthreads();
    }

    // Y epilogue
#pragma unroll
    for (int mi = 0; mi < 4; mi++) {
        int gr0 = rowBase + wm + mi * 16 + r4;
#pragma unroll
        for (int ni = 0; ni < 4; ni++) {
            int gc = colBase + wn + ni * 8 + q * 2;
            if (gr0 < M)
                *(__half2*)&g_Y[(size_t)gr0 * NCOL + gc] =
                    __floats2half2_rn(acc[mi][ni][0], acc[mi][ni][1]);
            if (gr0 + 8 < M)
                *(__half2*)&g_Y[(size_t)(gr0 + 8) * NCOL + gc] =
                    __floats2half2_rn(acc[mi][ni][2], acc[mi][ni][3]);
        }
    }

    // ---- band-completion counter: last two CTAs expand 64 rows each ----
    __threadfence();
    __syncthreads();
    __shared__ int s_old;
    if (tid == 0) s_old = atomicAdd(&bandcnt[blockIdx.y], 1);
    __syncthreads();
    int old = s_old;
    if (old >= 16) {
        __threadfence();   // acquire side
        int half = old - 16;             // 0 or 1
        int c0 = lane * 8;
#pragma unroll
        for (int i = 0; i < 8; i++) {
            int n = rowBase + half * 64 + wid * 8 + i;
            if (n >= M) continue;
            unsigned long long y[BB][4];
#pragma unroll
            for (int b = 0; b < BB; b++) {
                uint4 v = *(const uint4*)&g_Y[(size_t)n * NCOL + b * DD + c0];
                const __half2* hp = (const __half2*)&v;
#pragma unroll
                for (int j = 0; j < 4; j++) {
                    float2 p = __half22float2(hp[j]);
                    asm("mov.b64 %0, {%1, %2};" : "=l"(y[b][j]) : "f"(p.x), "f"(p.y));
                }
            }
#pragma unroll
            for (int r = 0; r < RR; r++) {
                unsigned long long a2[4] = {0ull, 0ull, 0ull, 0ull};
#pragma unroll
                for (int b = 0; b < BB; b++) {
                    unsigned long long ab = sap[r * BB + b];
#pragma unroll
                    for (int j = 0; j < 4; j++)
                        asm("fma.rn.f32x2 %0, %1, %2, %0;" : "+l"(a2[j]) : "l"(y[b][j]), "l"(ab));
                }
                uint4 hv;
                __half2* hp = (__half2*)&hv;
#pragma unroll
                for (int j = 0; j < 4; j++) {
                    float lo, hi;
                    asm("mov.b64 {%0, %1}, %2;" : "=f"(lo), "=f"(hi) : "l"(a2[j]));
                    hp[j] = __floats2half2_rn(lo, hi);
                }
                *(uint4*)&g_H[((size_t)n * RR + r) * DD + c0] = hv;
            }
        }
    }
}

// ===========================================================================
// Fused gather + finalize: one warp per dst node; edge loop unrolled x2.
__global__ __launch_bounds__(256) void k_gather_fin(
    const float* __restrict__ xin, const float* __restrict__ bias,
    const float* __restrict__ gln, const float* __restrict__ bln,
    float* __restrict__ out, int M, int emit_split) {
    int wid = threadIdx.x >> 5, lane = threadIdx.x & 31;
    int n = blockIdx.x * 8 + wid;
    if (n >= M) return;
    int start = g_rowptr[n];
    int deg = g_deg[n];
    int end = start + deg;

    float acc[8];
    {
        const uint4* hs = (const uint4*)&g_H[((size_t)n * RR + (RR - 1)) * DD];
        uint4 v = hs[lane];
        const __half2* hp = (const __half2*)&v;
#pragma unroll
        for (int j = 0; j < 4; j++) {
            float2 p = __half22float2(hp[j]);
            acc[2 * j] = p.x; acc[2 * j + 1] = p.y;
        }
    }
    int i = start;
    for (; i + 1 < end; i += 2) {
        uint32_t pk0 = g_epack[i], pk1 = g_epack[i + 1];
        float w0 = g_ew[i], w1 = g_ew[i + 1];
        const uint4* h0 = (const uint4*)&g_H[((size_t)(pk0 & 0xFFFF) * RR + (pk0 >> 16)) * DD];
        const uint4* h1 = (const uint4*)&g_H[((size_t)(pk1 & 0xFFFF) * RR + (pk1 >> 16)) * DD];
        uint4 u0 = h0[lane];
        uint4 u1 = h1[lane];
        const __half2* p0 = (const __half2*)&u0;
        const __half2* p1 = (const __half2*)&u1;
#pragma unroll
        for (int j = 0; j < 4; j++) {
            float2 a0 = __half22float2(p0[j]);
            float2 a1 = __half22float2(p1[j]);
            acc[2 * j]     += w0 * a0.x + w1 * a1.x;
            acc[2 * j + 1] += w0 * a0.y + w1 * a1.y;
        }
    }
    if (i < end) {
        uint32_t pk = g_epack[i];
        float w = g_ew[i];
        const uint4* h = (const uint4*)&g_H[((size_t)(pk & 0xFFFF) * RR + (pk >> 16)) * DD];
        uint4 u = h[lane];
        const __half2* up = (const __half2*)&u;
#pragma unroll
        for (int j = 0; j < 4; j++) {
            float2 p = __half22float2(up[j]);
            acc[2 * j]     += w * p.x;
            acc[2 * j + 1] += w * p.y;
        }
    }
    float inv = 1.0f / (float)(deg + 1);
    size_t no = (size_t)n * DD + lane * 8;
    int c0 = lane * 8;

    uint4 yv = *(const uint4*)&g_Y[(size_t)n * NCOL + BB * DD + c0];
    const __half2* yp = (const __half2*)&yv;
    float4 xv0 = *(const float4*)&xin[no];
    float4 xv1 = *(const float4*)&xin[no + 4];
    float4 bv0 = *(const float4*)&bias[c0];
    float4 bv1 = *(const float4*)&bias[c0 + 4];

    float val[8];
    {
        float2 y0 = __half22float2(yp[0]), y1 = __half22float2(yp[1]);
        float2 y2 = __half22float2(yp[2]), y3 = __half22float2(yp[3]);
        val[0] = acc[0] * inv + y0.x + bv0.x + xv0.x;
        val[1] = acc[1] * inv + y0.y + bv0.y + xv0.y;
        val[2] = acc[2] * inv + y1.x + bv0.z + xv0.z;
        val[3] = acc[3] * inv + y1.y + bv0.w + xv0.w;
        val[4] = acc[4] * inv + y2.x + bv1.x + xv1.x;
        val[5] = acc[5] * inv + y2.y + bv1.y + xv1.y;
        val[6] = acc[6] * inv + y3.x + bv1.z + xv1.z;
        val[7] = acc[7] * inv + y3.y + bv1.w + xv1.w;
    }
    float s = 0.f;
#pragma unroll
    for (int j = 0; j < 8; j++) s += val[j];
#pragma unroll
    for (int k = 16; k > 0; k >>= 1) s += __shfl_xor_sync(0xffffffffu, s, k);
    float mu = s * (1.0f / DD);
    float s2 = 0.f;
#pragma unroll
    for (int j = 0; j < 8; j++) { float d = val[j] - mu; s2 += d * d; }
#pragma unroll
    for (int k = 16; k > 0; k >>= 1) s2 += __shfl_xor_sync(0xffffffffu, s2, k);
    float rstd = rsqrtf(s2 * (1.0f / DD) + LN_EPS);

    float4 gv0 = *(const float4*)&gln[c0];
    float4 gv1 = *(const float4*)&gln[c0 + 4];
    float4 lb0 = *(const float4*)&bln[c0];
    float4 lb1 = *(const float4*)&bln[c0 + 4];
    float y[8];
    y[0] = fmaxf((val[0] - mu) * rstd * gv0.x + lb0.x, 0.f);
    y[1] = fmaxf((val[1] - mu) * rstd * gv0.y + lb0.y, 0.f);
    y[2] = fmaxf((val[2] - mu) * rstd * gv0.z + lb0.z, 0.f);
    y[3] = fmaxf((val[3] - mu) * rstd * gv0.w + lb0.w, 0.f);
    y[4] = fmaxf((val[4] - mu) * rstd * gv1.x + lb1.x, 0.f);
    y[5] = fmaxf((val[5] - mu) * rstd * gv1.y + lb1.y, 0.f);
    y[6] = fmaxf((val[6] - mu) * rstd * gv1.z + lb1.z, 0.f);
    y[7] = fmaxf((val[7] - mu) * rstd * gv1.w + lb1.w, 0.f);

    *(float4*)&out[no]     = make_float4(y[0], y[1], y[2], y[3]);
    *(float4*)&out[no + 4] = make_float4(y[4], y[5], y[6], y[7]);
    if (emit_split) {
        uint4 hv;
        __half2* hp = (__half2*)&hv;
        hp[0] = __floats2half2_rn(y[0], y[1]);
        hp[1] = __floats2half2_rn(y[2], y[3]);
        hp[2] = __floats2half2_rn(y[4], y[5]);
        hp[3] = __floats2half2_rn(y[6], y[7]);
        *(uint4*)&g_Ap[(size_t)n * KK + c0] = hv;
    }
}

// ===========================================================================
static void run_layer(const float* x, const float* att,
                      const float* bias, const float* lg, const float* lb,
                      const __half* Bp, int* bandcnt, float* out, int M, int emit_split) {
    {
        dim3 grid(NCOL / 128, (M + 127) / 128);   // (18, 391)
        k_gemm_mma<<<grid, 256, SMEM_TOTAL>>>(M, Bp, bandcnt, att);
    }
    k_gather_fin<<<(M + 7) / 8, 256>>>(x, bias, lg, lb, out, M, emit_split);
}

extern "C" void kernel_launch(void* const* d_in, const int* in_sizes, int n_in,
                              void* d_out, int out_size) {
    const float* x   = (const float*)d_in[0];
    const int*   ei  = (const int*)d_in[1];
    const int*   et  = (const int*)d_in[2];
    const float* ea  = (const float*)d_in[3];
    const float* basis1 = (const float*)d_in[4];
    const float* att1   = (const float*)d_in[5];
    const float* root1  = (const float*)d_in[6];
    const float* bias1  = (const float*)d_in[7];
    const float* ln1g   = (const float*)d_in[8];
    const float* ln1b   = (const float*)d_in[9];
    const float* basis2 = (const float*)d_in[10];
    const float* att2   = (const float*)d_in[11];
    const float* root2  = (const float*)d_in[12];
    const float* bias2  = (const float*)d_in[13];
    const float* ln2g   = (const float*)d_in[14];
    const float* ln2b   = (const float*)d_in[15];
    float* out = (float*)d_out;

    int M = in_sizes[0] / DD;     // 50000
    int E = in_sizes[2];          // 800000

    cudaFuncSetAttribute(k_gemm_mma, cudaFuncAttributeMaxDynamicSharedMemorySize,
                         SMEM_TOTAL);

    void* p = nullptr;
    cudaGetSymbolAddress(&p, g_x1);
    float* x1_dev = (float*)p;
    cudaGetSymbolAddress(&p, g_Bp1);
    __half* bp1_dev = (__half*)p;
    cudaGetSymbolAddress(&p, g_Bp2);
    __half* bp2_dev = (__half*)p;
    cudaGetSymbolAddress(&p, g_bc1);
    int* bc1_dev = (int*)p;
    cudaGetSymbolAddress(&p, g_bc2);
    int* bc2_dev = (int*)p;

    // Prep both layers' weights + input conversion + counter zero upfront
    k_prepw<<<NCOL, 256>>>(basis1, root1, bp1_dev);
    k_prepw<<<NCOL, 256>>>(basis2, root2, bp2_dev);
    k_cvt_x<<<(M * DD + 255) / 256, 256>>>(x, M);

    // CSR over dst (shared by both layers); also zeroes band counters
    int nb = (M + 255) / 256;                  // 196
    k_zero_degfill<<<nb, 256>>>(M);
    k_deg_count<<<(E + 255) / 256, 256>>>(ei, E);
    k_scan1<<<nb, 256>>>(M);
    k_scan2<<<1, 256>>>(nb);
    k_scan3<<<nb, 256>>>(M);
    k_fill<<<(E + 255) / 256, 256>>>(ei, et, ea, E);

    // layer 1
    run_layer(x, att1, bias1, ln1g, ln1b, bp1_dev, bc1_dev, x1_dev, M, 1);
    // layer 2 (g_Ap emitted by layer-1 gather_fin)
    run_layer(x1_dev, att2, bias2, ln2g, ln2b, bp2_dev, bc2_dev, out, M, 0);
}

// round 15
// speedup vs baseline: 1.0517x; 1.0517x over previous
#include <cuda_runtime.h>
#include <cuda_fp16.h>
#include <cstdint>

// Problem constants
#define NN 50000
#define DD 256
#define RR 16
#define BB 8
#define NCOL 2304               // 8 basis blocks + root = 9 * 256
#define KK 256                  // pure fp16 single-product GEMM
#define EE 800000
#define LN_EPS 1e-5f

// ---- static scratch ----
__device__ __half g_Ap[(size_t)NN * KK];     // fp16 activations [N,256]
__device__ __half g_Bp1[(size_t)NCOL * KK];  // fp16 weights layer 1
__device__ __half g_Bp2[(size_t)NCOL * KK];  // fp16 weights layer 2
__device__ __half g_Y[(size_t)NN * NCOL];    // x @ W  [N,2304] fp16
__device__ __half g_H[(size_t)NN * RR * DD]; // per-relation fp16
__device__ float g_x1[(size_t)NN * DD];      // layer-1 output
// CSR over dst
__device__ int g_deg[NN];
__device__ int g_rowptr[NN];
__device__ int g_bsum[256];
__device__ int g_fill[NN];
__device__ uint32_t g_epack[EE];             // src | (et << 16)
__device__ float g_ew[EE];

static __device__ __forceinline__ uint32_t s2u(const void* p) {
    uint32_t a;
    asm("{ .reg .u64 t; cvta.to.shared.u64 t, %1; cvt.u32.u64 %0, t; }" : "=r"(a) : "l"(p));
    return a;
}
#define CP_COMMIT() asm volatile("cp.async.commit_group;" ::: "memory")
#define CP_WAIT(n)  asm volatile("cp.async.wait_group %0;" :: "n"(n) : "memory")
#define LDSM4(r, addr) \
    asm volatile("ldmatrix.sync.aligned.m8n8.x4.shared.b16 {%0,%1,%2,%3}, [%4];" \
        : "=r"((r)[0]), "=r"((r)[1]), "=r"((r)[2]), "=r"((r)[3]) : "r"(addr))

// ===========================================================================
// CSR build
__global__ void k_zero_degfill(int M) {
    int t = blockIdx.x * 256 + threadIdx.x;
    if (t < M) { g_deg[t] = 0; g_fill[t] = 0; }
}
__global__ void k_deg_count(const int* __restrict__ ei, int E) {
    int t = blockIdx.x * 256 + threadIdx.x;
    if (t < E) atomicAdd(&g_deg[ei[E + t]], 1);
}
__global__ void k_scan1(int M) {
    __shared__ int s[256];
    int i = blockIdx.x * 256 + threadIdx.x;
    int v = (i < M) ? g_deg[i] : 0;
    s[threadIdx.x] = v;
    __syncthreads();
    for (int off = 1; off < 256; off <<= 1) {
        int t = (threadIdx.x >= off) ? s[threadIdx.x - off] : 0;
        __syncthreads();
        s[threadIdx.x] += t;
        __syncthreads();
    }
    if (i < M) g_rowptr[i] = s[threadIdx.x] - v;
    if (threadIdx.x == 255) g_bsum[blockIdx.x] = s[255];
}
__global__ void k_scan2(int nb) {
    __shared__ int s[256];
    int v = (threadIdx.x < nb) ? g_bsum[threadIdx.x] : 0;
    s[threadIdx.x] = v;
    __syncthreads();
    for (int off = 1; off < 256; off <<= 1) {
        int t = (threadIdx.x >= off) ? s[threadIdx.x - off] : 0;
        __syncthreads();
        s[threadIdx.x] += t;
        __syncthreads();
    }
    g_bsum[threadIdx.x] = s[threadIdx.x] - v;
}
__global__ void k_scan3(int M) {
    int i = blockIdx.x * 256 + threadIdx.x;
    if (i < M) g_rowptr[i] += g_bsum[i >> 8];
}
__global__ void k_fill(const int* __restrict__ ei, const int* __restrict__ et,
                       const float* __restrict__ ea, int E) {
    int t = blockIdx.x * 256 + threadIdx.x;
    if (t >= E) return;
    int dst = ei[E + t];
    int slot = atomicAdd(&g_fill[dst], 1);
    int idx = g_rowptr[dst] + slot;
    g_epack[idx] = (uint32_t)ei[t] | ((uint32_t)et[t] << 16);
    g_ew[idx] = ea[t];
}

// ===========================================================================
// Prep: fp16 weights into the given buffer (both layers prepped upfront)
__global__ void k_prepw(const float* __restrict__ basis, const float* __restrict__ root,
                        __half* __restrict__ Bp) {
    int c = blockIdx.x;      // 0..2303
    int k = threadIdx.x;     // 0..255
    float w;
    if (c < BB * DD) {
        int b = c >> 8, o = c & 255;
        w = basis[((size_t)b * DD + k) * DD + o];
    } else {
        w = root[(size_t)k * DD + (c - BB * DD)];
    }
    Bp[(size_t)c * KK + k] = __float2half_rn(w);
}
__global__ void k_cvt_x(const float* __restrict__ x, int M) {
    int t = blockIdx.x * 256 + threadIdx.x;
    if (t >= M * DD) return;
    g_Ap[t] = __float2half_rn(x[t]);
}

// ===========================================================================
// fp16 mma.sync GEMM (R11/R13 core; weights via pointer arg)
#define BK 64
#define TILE_B 18432

static __device__ __forceinline__ void mma16816(float* c, const uint32_t* a,
                                                const uint32_t* b) {
    asm volatile(
        "mma.sync.aligned.m16n8k16.row.col.f32.f16.f16.f32 "
        "{%0,%1,%2,%3}, {%4,%5,%6,%7}, {%8,%9}, {%0,%1,%2,%3};\n"
        : "+f"(c[0]), "+f"(c[1]), "+f"(c[2]), "+f"(c[3])
        : "r"(a[0]), "r"(a[1]), "r"(a[2]), "r"(a[3]), "r"(b[0]), "r"(b[1]));
}

__global__ __launch_bounds__(256, 2) void k_gemm_mma(int M, const __half* __restrict__ Bp) {
    extern __shared__ char smem[];
    const uint32_t sbase = s2u(smem);
    const int tid = threadIdx.x;
    const int wid = tid >> 5, lane = tid & 31;
    const int r4 = lane >> 2, q = lane & 3;
    const int rowBase = blockIdx.y * 128;
    const int colBase = blockIdx.x * 128;
    const int wm = (wid >> 2) * 64;
    const int wn = (wid & 3) * 32;

    float acc[4][4][4];
#pragma unroll
    for (int i = 0; i < 4; i++)
#pragma unroll
        for (int j = 0; j < 4; j++)
#pragma unroll
            for (int t = 0; t < 4; t++) acc[i][j][t] = 0.f;

    uint32_t aOff[4];
#pragma unroll
    for (int mi = 0; mi < 4; mi++)
        aOff[mi] = (uint32_t)((wm + mi * 16 + (lane & 15)) * 144 + ((lane >> 4) & 1) * 16);
    uint32_t bOff[2];
#pragma unroll
    for (int p = 0; p < 2; p++)
        bOff[p] = (uint32_t)((wn + p * 16 + ((lane & 16) >> 1) + (lane & 7)) * 144
                             + ((lane >> 3) & 1) * 16);

    auto issueTiles = [&](int kt, int buf) {
        int k0 = kt * BK;
        uint32_t sa = sbase + buf * TILE_B;
        uint32_t sb = sbase + 2 * TILE_B + buf * TILE_B;
#pragma unroll
        for (int i = 0; i < 4; i++) {
            int e = tid + i * 256;
            int r = e >> 3, c8 = e & 7;
            int gr = rowBase + r;
            uint32_t sz = (gr < M) ? 16u : 0u;
            const void* src = &g_Ap[(size_t)(gr < M ? gr : 0) * KK + k0 + c8 * 8];
            asm volatile("cp.async.cg.shared.global [%0], [%1], 16, %2;"
                         :: "r"(sa + r * 144 + c8 * 16), "l"(src), "r"(sz));
        }
#pragma unroll
        for (int i = 0; i < 4; i++) {
            int e = tid + i * 256;
            int r = e >> 3, c8 = e & 7;
            const void* src = &Bp[(size_t)(colBase + r) * KK + k0 + c8 * 8];
            asm volatile("cp.async.cg.shared.global [%0], [%1], 16;"
                         :: "r"(sb + r * 144 + c8 * 16), "l"(src));
        }
    };

    const int NT = KK / BK;   // 4
    issueTiles(0, 0);
    CP_COMMIT();

    for (int kt = 0; kt < NT; kt++) {
        int buf = kt & 1;
        if (kt + 1 < NT) {
            issueTiles(kt + 1, buf ^ 1);
            CP_COMMIT();
            CP_WAIT(1);
        } else {
            CP_WAIT(0);
        }
        __syncthreads();

        uint32_t sa = sbase + buf * TILE_B;
        uint32_t sb = sbase + 2 * TILE_B + buf * TILE_B;
#pragma unroll
        for (int ks = 0; ks < 4; ks++) {
            uint32_t af[4][4], bf[2][4];
#pragma unroll
            for (int mi = 0; mi < 4; mi++) LDSM4(af[mi], sa + aOff[mi] + ks * 32);
#pragma unroll
            for (int p = 0; p < 2; p++)    LDSM4(bf[p], sb + bOff[p] + ks * 32);
#pragma unroll
            for (int mi = 0; mi < 4; mi++)
#pragma unroll
                for (int ni = 0; ni < 4; ni++)
                    mma16816(acc[mi][ni], af[mi], &bf[ni >> 1][(ni & 1) * 2]);
        }
        __syncthreads();
    }

#pragma unroll
    for (int mi = 0; mi < 4; mi++) {
        int gr0 = rowBase + wm + mi * 16 + r4;
#pragma unroll
        for (int ni = 0; ni < 4; ni++) {
            int gc = colBase + wn + ni * 8 + q * 2;
            if (gr0 < M)
                *(__half2*)&g_Y[(size_t)gr0 * NCOL + gc] =
                    __floats2half2_rn(acc[mi][ni][0], acc[mi][ni][1]);
            if (gr0 + 8 < M)
                *(__half2*)&g_Y[(size_t)(gr0 + 8) * NCOL + gc] =
                    __floats2half2_rn(acc[mi][ni][2], acc[mi][ni][3]);
        }
    }
}

// ===========================================================================
// Expand: H[n,r,o] = sum_b att[r,b] * Y[n, b*256+o]
// One warp per node; packed f32x2 FMA.
__global__ __launch_bounds__(256) void k_expand(const float* __restrict__ att, int M) {
    __shared__ unsigned long long ap[RR * BB];
    if (threadIdx.x < RR * BB) {
        float v = att[threadIdx.x];
        unsigned long long pk;
        asm("mov.b64 %0, {%1, %2};" : "=l"(pk) : "f"(v), "f"(v));
        ap[threadIdx.x] = pk;
    }
    __syncthreads();
    int n = blockIdx.x * 8 + (threadIdx.x >> 5);
    if (n >= M) return;
    int lane = threadIdx.x & 31;
    int c0 = lane * 8;
    unsigned long long y[BB][4];
#pragma unroll
    for (int b = 0; b < BB; b++) {
        uint4 v = *(const uint4*)&g_Y[(size_t)n * NCOL + b * DD + c0];
        const __half2* hp = (const __half2*)&v;
#pragma unroll
        for (int j = 0; j < 4; j++) {
            float2 p = __half22float2(hp[j]);
            asm("mov.b64 %0, {%1, %2};" : "=l"(y[b][j]) : "f"(p.x), "f"(p.y));
        }
    }
#pragma unroll
    for (int r = 0; r < RR; r++) {
        unsigned long long acc[4] = {0ull, 0ull, 0ull, 0ull};
#pragma unroll
        for (int b = 0; b < BB; b++) {
            unsigned long long ab = ap[r * BB + b];
#pragma unroll
            for (int j = 0; j < 4; j++)
                asm("fma.rn.f32x2 %0, %1, %2, %0;" : "+l"(acc[j]) : "l"(y[b][j]), "l"(ab));
        }
        uint4 hv;
        __half2* hp = (__half2*)&hv;
#pragma unroll
        for (int j = 0; j < 4; j++) {
            float lo, hi;
            asm("mov.b64 {%0, %1}, %2;" : "=f"(lo), "=f"(hi) : "l"(acc[j]));
            hp[j] = __floats2half2_rn(lo, hi);
        }
        *(uint4*)&g_H[((size_t)n * RR + r) * DD + c0] = hv;
    }
}

// ===========================================================================
// Fused gather + finalize: one warp per dst node; edge loop unrolled x4 (MLP=4),
// H gathers through the non-coherent (L1-cached) path.
__global__ __launch_bounds__(256) void k_gather_fin(
    const float* __restrict__ xin, const float* __restrict__ bias,
    const float* __restrict__ gln, const float* __restrict__ bln,
    float* __restrict__ out, int M, int emit_split) {
    int wid = threadIdx.x >> 5, lane = threadIdx.x & 31;
    int n = blockIdx.x * 8 + wid;
    if (n >= M) return;
    int start = g_rowptr[n];
    int deg = g_deg[n];
    int end = start + deg;

    float acc[8];
    {
        uint4 v = __ldg((const uint4*)&g_H[((size_t)n * RR + (RR - 1)) * DD] + lane);
        const __half2* hp = (const __half2*)&v;
#pragma unroll
        for (int j = 0; j < 4; j++) {
            float2 p = __half22float2(hp[j]);
            acc[2 * j] = p.x; acc[2 * j + 1] = p.y;
        }
    }
    int i = start;
    for (; i + 3 < end; i += 4) {
        uint32_t pk0 = g_epack[i],     pk1 = g_epack[i + 1];
        uint32_t pk2 = g_epack[i + 2], pk3 = g_epack[i + 3];
        float w0 = g_ew[i],     w1 = g_ew[i + 1];
        float w2 = g_ew[i + 2], w3 = g_ew[i + 3];
        uint4 u0 = __ldg((const uint4*)&g_H[((size_t)(pk0 & 0xFFFF) * RR + (pk0 >> 16)) * DD] + lane);
        uint4 u1 = __ldg((const uint4*)&g_H[((size_t)(pk1 & 0xFFFF) * RR + (pk1 >> 16)) * DD] + lane);
        uint4 u2 = __ldg((const uint4*)&g_H[((size_t)(pk2 & 0xFFFF) * RR + (pk2 >> 16)) * DD] + lane);
        uint4 u3 = __ldg((const uint4*)&g_H[((size_t)(pk3 & 0xFFFF) * RR + (pk3 >> 16)) * DD] + lane);
        const __half2* p0 = (const __half2*)&u0;
        const __half2* p1 = (const __half2*)&u1;
        const __half2* p2 = (const __half2*)&u2;
        const __half2* p3 = (const __half2*)&u3;
#pragma unroll
        for (int j = 0; j < 4; j++) {
            float2 a0 = __half22float2(p0[j]);
            float2 a1 = __half22float2(p1[j]);
            float2 a2 = __half22float2(p2[j]);
            float2 a3 = __half22float2(p3[j]);
            acc[2 * j]     += w0 * a0.x + w1 * a1.x + w2 * a2.x + w3 * a3.x;
            acc[2 * j + 1] += w0 * a0.y + w1 * a1.y + w2 * a2.y + w3 * a3.y;
        }
    }
    for (; i < end; i++) {
        uint32_t pk = g_epack[i];
        float w = g_ew[i];
        uint4 u = __ldg((const uint4*)&g_H[((size_t)(pk & 0xFFFF) * RR + (pk >> 16)) * DD] + lane);
        const __half2* up = (const __half2*)&u;
#pragma unroll
        for (int j = 0; j < 4; j++) {
            float2 p = __half22float2(up[j]);
            acc[2 * j]     += w * p.x;
            acc[2 * j + 1] += w * p.y;
        }
    }
    float inv = 1.0f / (float)(deg + 1);
    size_t no = (size_t)n * DD + lane * 8;
    int c0 = lane * 8;

    uint4 yv = *(const uint4*)&g_Y[(size_t)n * NCOL + BB * DD + c0];
    const __half2* yp = (const __half2*)&yv;
    float4 xv0 = *(const float4*)&xin[no];
    float4 xv1 = *(const float4*)&xin[no + 4];
    float4 bv0 = *(const float4*)&bias[c0];
    float4 bv1 = *(const float4*)&bias[c0 + 4];

    float val[8];
    {
        float2 y0 = __half22float2(yp[0]), y1 = __half22float2(yp[1]);
        float2 y2 = __half22float2(yp[2]), y3 = __half22float2(yp[3]);
        val[0] = acc[0] * inv + y0.x + bv0.x + xv0.x;
        val[1] = acc[1] * inv + y0.y + bv0.y + xv0.y;
        val[2] = acc[2] * inv + y1.x + bv0.z + xv0.z;
        val[3] = acc[3] * inv + y1.y + bv0.w + xv0.w;
        val[4] = acc[4] * inv + y2.x + bv1.x + xv1.x;
        val[5] = acc[5] * inv + y2.y + bv1.y + xv1.y;
        val[6] = acc[6] * inv + y3.x + bv1.z + xv1.z;
        val[7] = acc[7] * inv + y3.y + bv1.w + xv1.w;
    }
    float s = 0.f;
#pragma unroll
    for (int j = 0; j < 8; j++) s += val[j];
#pragma unroll
    for (int k = 16; k > 0; k >>= 1) s += __shfl_xor_sync(0xffffffffu, s, k);
    float mu = s * (1.0f / DD);
    float s2 = 0.f;
#pragma unroll
    for (int j = 0; j < 8; j++) { float d = val[j] - mu; s2 += d * d; }
#pragma unroll
    for (int k = 16; k > 0; k >>= 1) s2 += __shfl_xor_sync(0xffffffffu, s2, k);
    float rstd = rsqrtf(s2 * (1.0f / DD) + LN_EPS);

    float4 gv0 = *(const float4*)&gln[c0];
    float4 gv1 = *(const float4*)&gln[c0 + 4];
    float4 lb0 = *(const float4*)&bln[c0];
    float4 lb1 = *(const float4*)&bln[c0 + 4];
    float y[8];
    y[0] = fmaxf((val[0] - mu) * rstd * gv0.x + lb0.x, 0.f);
    y[1] = fmaxf((val[1] - mu) * rstd * gv0.y + lb0.y, 0.f);
    y[2] = fmaxf((val[2] - mu) * rstd * gv0.z + lb0.z, 0.f);
    y[3] = fmaxf((val[3] - mu) * rstd * gv0.w + lb0.w, 0.f);
    y[4] = fmaxf((val[4] - mu) * rstd * gv1.x + lb1.x, 0.f);
    y[5] = fmaxf((val[5] - mu) * rstd * gv1.y + lb1.y, 0.f);
    y[6] = fmaxf((val[6] - mu) * rstd * gv1.z + lb1.z, 0.f);
    y[7] = fmaxf((val[7] - mu) * rstd * gv1.w + lb1.w, 0.f);

    *(float4*)&out[no]     = make_float4(y[0], y[1], y[2], y[3]);
    *(float4*)&out[no + 4] = make_float4(y[4], y[5], y[6], y[7]);
    if (emit_split) {
        uint4 hv;
        __half2* hp = (__half2*)&hv;
        hp[0] = __floats2half2_rn(y[0], y[1]);
        hp[1] = __floats2half2_rn(y[2], y[3]);
        hp[2] = __floats2half2_rn(y[4], y[5]);
        hp[3] = __floats2half2_rn(y[6], y[7]);
        *(uint4*)&g_Ap[(size_t)n * KK + c0] = hv;
    }
}

// ===========================================================================
static void run_layer(const float* x, const float* att,
                      const float* bias, const float* lg, const float* lb,
                      const __half* Bp, float* out, int M, int emit_split) {
    {
        dim3 grid(NCOL / 128, (M + 127) / 128);   // (18, 391)
        k_gemm_mma<<<grid, 256, 4 * TILE_B>>>(M, Bp);
    }
    k_expand<<<(M + 7) / 8, 256>>>(att, M);
    k_gather_fin<<<(M + 7) / 8, 256>>>(x, bias, lg, lb, out, M, emit_split);
}

extern "C" void kernel_launch(void* const* d_in, const int* in_sizes, int n_in,
                              void* d_out, int out_size) {
    const float* x   = (const float*)d_in[0];
    const int*   ei  = (const int*)d_in[1];
    const int*   et  = (const int*)d_in[2];
    const float* ea  = (const float*)d_in[3];
    const float* basis1 = (const float*)d_in[4];
    const float* att1   = (const float*)d_in[5];
    const float* root1  = (const float*)d_in[6];
    const float* bias1  = (const float*)d_in[7];
    const float* ln1g   = (const float*)d_in[8];
    const float* ln1b   = (const float*)d_in[9];
    const float* basis2 = (const float*)d_in[10];
    const float* att2   = (const float*)d_in[11];
    const float* root2  = (const float*)d_in[12];
    const float* bias2  = (const float*)d_in[13];
    const float* ln2g   = (const float*)d_in[14];
    const float* ln2b   = (const float*)d_in[15];
    float* out = (float*)d_out;

    int M = in_sizes[0] / DD;     // 50000
    int E = in_sizes[2];          // 800000

    cudaFuncSetAttribute(k_gemm_mma, cudaFuncAttributeMaxDynamicSharedMemorySize,
                         4 * TILE_B);

    void* p = nullptr;
    cudaGetSymbolAddress(&p, g_x1);
    float* x1_dev = (float*)p;
    cudaGetSymbolAddress(&p, g_Bp1);
    __half* bp1_dev = (__half*)p;
    cudaGetSymbolAddress(&p, g_Bp2);
    __half* bp2_dev = (__half*)p;

    // Prep both layers' weights + input conversion upfront
    k_prepw<<<NCOL, 256>>>(basis1, root1, bp1_dev);
    k_prepw<<<NCOL, 256>>>(basis2, root2, bp2_dev);
    k_cvt_x<<<(M * DD + 255) / 256, 256>>>(x, M);

    // CSR over dst (shared by both layers)
    int nb = (M + 255) / 256;                  // 196
    k_zero_degfill<<<nb, 256>>>(M);
    k_deg_count<<<(E + 255) / 256, 256>>>(ei, E);
    k_scan1<<<nb, 256>>>(M);
    k_scan2<<<1, 256>>>(nb);
    k_scan3<<<nb, 256>>>(M);
    k_fill<<<(E + 255) / 256, 256>>>(ei, et, ea, E);

    // layer 1
    run_layer(x, att1, bias1, ln1g, ln1b, bp1_dev, x1_dev, M, 1);
    // layer 2 (g_Ap emitted by layer-1 gather_fin)
    run_layer(x1_dev, att2, bias2, ln2g, ln2b, bp2_dev, out, M, 0);
}

// round 16
// speedup vs baseline: 1.0763x; 1.0235x over previous
#include <cuda_runtime.h>
#include <cuda_fp16.h>
#include <cstdint>

// Problem constants
#define NN 50000
#define DD 256
#define RR 16
#define BB 8
#define NCOL 2304               // 8 basis blocks + root = 9 * 256
#define KK 256                  // pure fp16 single-product GEMM
#define EE 800000
#define LN_EPS 1e-5f

// ---- static scratch ----
__device__ __half g_Ap[(size_t)NN * KK];     // fp16 activations [N,256]
__device__ __half g_Bp1[(size_t)NCOL * KK];  // fp16 weights layer 1
__device__ __half g_Bp2[(size_t)NCOL * KK];  // fp16 weights layer 2
__device__ __half g_Y[(size_t)NN * NCOL];    // x @ W  [N,2304] fp16
__device__ __half g_H[(size_t)NN * RR * DD]; // per-relation fp16
__device__ float g_x1[(size_t)NN * DD];      // layer-1 output
// CSR over dst + used-pair bitmap over src
__device__ int g_deg[NN];
__device__ int g_rowptr[NN];
__device__ int g_bsum[256];
__device__ int g_fill[NN];
__device__ uint32_t g_used[NN];              // bit r set iff some edge has (src=n, et=r)
__device__ uint32_t g_epack[EE];             // src | (et << 16)
__device__ float g_ew[EE];

static __device__ __forceinline__ uint32_t s2u(const void* p) {
    uint32_t a;
    asm("{ .reg .u64 t; cvta.to.shared.u64 t, %1; cvt.u32.u64 %0, t; }" : "=r"(a) : "l"(p));
    return a;
}
#define CP_COMMIT() asm volatile("cp.async.commit_group;" ::: "memory")
#define CP_WAIT(n)  asm volatile("cp.async.wait_group %0;" :: "n"(n) : "memory")
#define LDSM4(r, addr) \
    asm volatile("ldmatrix.sync.aligned.m8n8.x4.shared.b16 {%0,%1,%2,%3}, [%4];" \
        : "=r"((r)[0]), "=r"((r)[1]), "=r"((r)[2]), "=r"((r)[3]) : "r"(addr))

// ===========================================================================
// CSR build
__global__ void k_zero_degfill(int M) {
    int t = blockIdx.x * 256 + threadIdx.x;
    if (t < M) { g_deg[t] = 0; g_fill[t] = 0; g_used[t] = 0u; }
}
__global__ void k_deg_count(const int* __restrict__ ei, int E) {
    int t = blockIdx.x * 256 + threadIdx.x;
    if (t < E) atomicAdd(&g_deg[ei[E + t]], 1);
}
__global__ void k_scan1(int M) {
    __shared__ int s[256];
    int i = blockIdx.x * 256 + threadIdx.x;
    int v = (i < M) ? g_deg[i] : 0;
    s[threadIdx.x] = v;
    __syncthreads();
    for (int off = 1; off < 256; off <<= 1) {
        int t = (threadIdx.x >= off) ? s[threadIdx.x - off] : 0;
        __syncthreads();
        s[threadIdx.x] += t;
        __syncthreads();
    }
    if (i < M) g_rowptr[i] = s[threadIdx.x] - v;
    if (threadIdx.x == 255) g_bsum[blockIdx.x] = s[255];
}
__global__ void k_scan2(int nb) {
    __shared__ int s[256];
    int v = (threadIdx.x < nb) ? g_bsum[threadIdx.x] : 0;
    s[threadIdx.x] = v;
    __syncthreads();
    for (int off = 1; off < 256; off <<= 1) {
        int t = (threadIdx.x >= off) ? s[threadIdx.x - off] : 0;
        __syncthreads();
        s[threadIdx.x] += t;
        __syncthreads();
    }
    g_bsum[threadIdx.x] = s[threadIdx.x] - v;
}
__global__ void k_scan3(int M) {
    int i = blockIdx.x * 256 + threadIdx.x;
    if (i < M) g_rowptr[i] += g_bsum[i >> 8];
}
__global__ void k_fill(const int* __restrict__ ei, const int* __restrict__ et,
                       const float* __restrict__ ea, int E) {
    int t = blockIdx.x * 256 + threadIdx.x;
    if (t >= E) return;
    int dst = ei[E + t];
    int src = ei[t];
    int r = et[t];
    int slot = atomicAdd(&g_fill[dst], 1);
    int idx = g_rowptr[dst] + slot;
    g_epack[idx] = (uint32_t)src | ((uint32_t)r << 16);
    g_ew[idx] = ea[t];
    atomicOr(&g_used[src], 1u << r);
}

// ===========================================================================
// Prep: fp16 weights into the given buffer (both layers prepped upfront)
__global__ void k_prepw(const float* __restrict__ basis, const float* __restrict__ root,
                        __half* __restrict__ Bp) {
    int c = blockIdx.x;      // 0..2303
    int k = threadIdx.x;     // 0..255
    float w;
    if (c < BB * DD) {
        int b = c >> 8, o = c & 255;
        w = basis[((size_t)b * DD + k) * DD + o];
    } else {
        w = root[(size_t)k * DD + (c - BB * DD)];
    }
    Bp[(size_t)c * KK + k] = __float2half_rn(w);
}
__global__ void k_cvt_x(const float* __restrict__ x, int M) {
    int t = blockIdx.x * 256 + threadIdx.x;
    if (t >= M * DD) return;
    g_Ap[t] = __float2half_rn(x[t]);
}

// ===========================================================================
// fp16 mma.sync GEMM (R13/R15 core; weights via pointer arg)
#define BK 64
#define TILE_B 18432

static __device__ __forceinline__ void mma16816(float* c, const uint32_t* a,
                                                const uint32_t* b) {
    asm volatile(
        "mma.sync.aligned.m16n8k16.row.col.f32.f16.f16.f32 "
        "{%0,%1,%2,%3}, {%4,%5,%6,%7}, {%8,%9}, {%0,%1,%2,%3};\n"
        : "+f"(c[0]), "+f"(c[1]), "+f"(c[2]), "+f"(c[3])
        : "r"(a[0]), "r"(a[1]), "r"(a[2]), "r"(a[3]), "r"(b[0]), "r"(b[1]));
}

__global__ __launch_bounds__(256, 2) void k_gemm_mma(int M, const __half* __restrict__ Bp) {
    extern __shared__ char smem[];
    const uint32_t sbase = s2u(smem);
    const int tid = threadIdx.x;
    const int wid = tid >> 5, lane = tid & 31;
    const int r4 = lane >> 2, q = lane & 3;
    const int rowBase = blockIdx.y * 128;
    const int colBase = blockIdx.x * 128;
    const int wm = (wid >> 2) * 64;
    const int wn = (wid & 3) * 32;

    float acc[4][4][4];
#pragma unroll
    for (int i = 0; i < 4; i++)
#pragma unroll
        for (int j = 0; j < 4; j++)
#pragma unroll
            for (int t = 0; t < 4; t++) acc[i][j][t] = 0.f;

    uint32_t aOff[4];
#pragma unroll
    for (int mi = 0; mi < 4; mi++)
        aOff[mi] = (uint32_t)((wm + mi * 16 + (lane & 15)) * 144 + ((lane >> 4) & 1) * 16);
    uint32_t bOff[2];
#pragma unroll
    for (int p = 0; p < 2; p++)
        bOff[p] = (uint32_t)((wn + p * 16 + ((lane & 16) >> 1) + (lane & 7)) * 144
                             + ((lane >> 3) & 1) * 16);

    auto issueTiles = [&](int kt, int buf) {
        int k0 = kt * BK;
        uint32_t sa = sbase + buf * TILE_B;
        uint32_t sb = sbase + 2 * TILE_B + buf * TILE_B;
#pragma unroll
        for (int i = 0; i < 4; i++) {
            int e = tid + i * 256;
            int r = e >> 3, c8 = e & 7;
            int gr = rowBase + r;
            uint32_t sz = (gr < M) ? 16u : 0u;
            const void* src = &g_Ap[(size_t)(gr < M ? gr : 0) * KK + k0 + c8 * 8];
            asm volatile("cp.async.cg.shared.global [%0], [%1], 16, %2;"
                         :: "r"(sa + r * 144 + c8 * 16), "l"(src), "r"(sz));
        }
#pragma unroll
        for (int i = 0; i < 4; i++) {
            int e = tid + i * 256;
            int r = e >> 3, c8 = e & 7;
            const void* src = &Bp[(size_t)(colBase + r) * KK + k0 + c8 * 8];
            asm volatile("cp.async.cg.shared.global [%0], [%1], 16;"
                         :: "r"(sb + r * 144 + c8 * 16), "l"(src));
        }
    };

    const int NT = KK / BK;   // 4
    issueTiles(0, 0);
    CP_COMMIT();

    for (int kt = 0; kt < NT; kt++) {
        int buf = kt & 1;
        if (kt + 1 < NT) {
            issueTiles(kt + 1, buf ^ 1);
            CP_COMMIT();
            CP_WAIT(1);
        } else {
            CP_WAIT(0);
        }
        __syncthreads();

        uint32_t sa = sbase + buf * TILE_B;
        uint32_t sb = sbase + 2 * TILE_B + buf * TILE_B;
#pragma unroll
        for (int ks = 0; ks < 4; ks++) {
            uint32_t af[4][4], bf[2][4];
#pragma unroll
            for (int mi = 0; mi < 4; mi++) LDSM4(af[mi], sa + aOff[mi] + ks * 32);
#pragma unroll
            for (int p = 0; p < 2; p++)    LDSM4(bf[p], sb + bOff[p] + ks * 32);
#pragma unroll
            for (int mi = 0; mi < 4; mi++)
#pragma unroll
                for (int ni = 0; ni < 4; ni++)
                    mma16816(acc[mi][ni], af[mi], &bf[ni >> 1][(ni & 1) * 2]);
        }
        __syncthreads();
    }

#pragma unroll
    for (int mi = 0; mi < 4; mi++) {
        int gr0 = rowBase + wm + mi * 16 + r4;
#pragma unroll
        for (int ni = 0; ni < 4; ni++) {
            int gc = colBase + wn + ni * 8 + q * 2;
            if (gr0 < M)
                *(__half2*)&g_Y[(size_t)gr0 * NCOL + gc] =
                    __floats2half2_rn(acc[mi][ni][0], acc[mi][ni][1]);
            if (gr0 + 8 < M)
                *(__half2*)&g_Y[(size_t)(gr0 + 8) * NCOL + gc] =
                    __floats2half2_rn(acc[mi][ni][2], acc[mi][ni][3]);
        }
    }
}

// ===========================================================================
// Expand: H[n,r,o] = sum_b att[r,b] * Y[n, b*256+o]
// One warp per node; packed f32x2 FMA; rows for unused (n,r) pairs skipped
// (bitmap built during CSR fill; bit R-1 forced for the self-loop).
__global__ __launch_bounds__(256) void k_expand(const float* __restrict__ att, int M) {
    __shared__ unsigned long long ap[RR * BB];
    if (threadIdx.x < RR * BB) {
        float v = att[threadIdx.x];
        unsigned long long pk;
        asm("mov.b64 %0, {%1, %2};" : "=l"(pk) : "f"(v), "f"(v));
        ap[threadIdx.x] = pk;
    }
    __syncthreads();
    int n = blockIdx.x * 8 + (threadIdx.x >> 5);
    if (n >= M) return;
    int lane = threadIdx.x & 31;
    int c0 = lane * 8;
    uint32_t used = g_used[n] | (1u << (RR - 1));
    unsigned long long y[BB][4];
#pragma unroll
    for (int b = 0; b < BB; b++) {
        uint4 v = *(const uint4*)&g_Y[(size_t)n * NCOL + b * DD + c0];
        const __half2* hp = (const __half2*)&v;
#pragma unroll
        for (int j = 0; j < 4; j++) {
            float2 p = __half22float2(hp[j]);
            asm("mov.b64 %0, {%1, %2};" : "=l"(y[b][j]) : "f"(p.x), "f"(p.y));
        }
    }
#pragma unroll
    for (int r = 0; r < RR; r++) {
        if (!(used & (1u << r))) continue;   // warp-uniform skip
        unsigned long long acc[4] = {0ull, 0ull, 0ull, 0ull};
#pragma unroll
        for (int b = 0; b < BB; b++) {
            unsigned long long ab = ap[r * BB + b];
#pragma unroll
            for (int j = 0; j < 4; j++)
                asm("fma.rn.f32x2 %0, %1, %2, %0;" : "+l"(acc[j]) : "l"(y[b][j]), "l"(ab));
        }
        uint4 hv;
        __half2* hp = (__half2*)&hv;
#pragma unroll
        for (int j = 0; j < 4; j++) {
            float lo, hi;
            asm("mov.b64 {%0, %1}, %2;" : "=f"(lo), "=f"(hi) : "l"(acc[j]));
            hp[j] = __floats2half2_rn(lo, hi);
        }
        *(uint4*)&g_H[((size_t)n * RR + r) * DD + c0] = hv;
    }
}

// ===========================================================================
// Fused gather + finalize: one warp per dst node; edge loop unrolled x4,
// H gathers through the non-coherent (L1-cached) path.
__global__ __launch_bounds__(256) void k_gather_fin(
    const float* __restrict__ xin, const float* __restrict__ bias,
    const float* __restrict__ gln, const float* __restrict__ bln,
    float* __restrict__ out, int M, int emit_split) {
    int wid = threadIdx.x >> 5, lane = threadIdx.x & 31;
    int n = blockIdx.x * 8 + wid;
    if (n >= M) return;
    int start = g_rowptr[n];
    int deg = g_deg[n];
    int end = start + deg;

    float acc[8];
    {
        uint4 v = __ldg((const uint4*)&g_H[((size_t)n * RR + (RR - 1)) * DD] + lane);
        const __half2* hp = (const __half2*)&v;
#pragma unroll
        for (int j = 0; j < 4; j++) {
            float2 p = __half22float2(hp[j]);
            acc[2 * j] = p.x; acc[2 * j + 1] = p.y;
        }
    }
    int i = start;
    for (; i + 3 < end; i += 4) {
        uint32_t pk0 = g_epack[i],     pk1 = g_epack[i + 1];
        uint32_t pk2 = g_epack[i + 2], pk3 = g_epack[i + 3];
        float w0 = g_ew[i],     w1 = g_ew[i + 1];
        float w2 = g_ew[i + 2], w3 = g_ew[i + 3];
        uint4 u0 = __ldg((const uint4*)&g_H[((size_t)(pk0 & 0xFFFF) * RR + (pk0 >> 16)) * DD] + lane);
        uint4 u1 = __ldg((const uint4*)&g_H[((size_t)(pk1 & 0xFFFF) * RR + (pk1 >> 16)) * DD] + lane);
        uint4 u2 = __ldg((const uint4*)&g_H[((size_t)(pk2 & 0xFFFF) * RR + (pk2 >> 16)) * DD] + lane);
        uint4 u3 = __ldg((const uint4*)&g_H[((size_t)(pk3 & 0xFFFF) * RR + (pk3 >> 16)) * DD] + lane);
        const __half2* p0 = (const __half2*)&u0;
        const __half2* p1 = (const __half2*)&u1;
        const __half2* p2 = (const __half2*)&u2;
        const __half2* p3 = (const __half2*)&u3;
#pragma unroll
        for (int j = 0; j < 4; j++) {
            float2 a0 = __half22float2(p0[j]);
            float2 a1 = __half22float2(p1[j]);
            float2 a2 = __half22float2(p2[j]);
            float2 a3 = __half22float2(p3[j]);
            acc[2 * j]     += w0 * a0.x + w1 * a1.x + w2 * a2.x + w3 * a3.x;
            acc[2 * j + 1] += w0 * a0.y + w1 * a1.y + w2 * a2.y + w3 * a3.y;
        }
    }
    for (; i < end; i++) {
        uint32_t pk = g_epack[i];
        float w = g_ew[i];
        uint4 u = __ldg((const uint4*)&g_H[((size_t)(pk & 0xFFFF) * RR + (pk >> 16)) * DD] + lane);
        const __half2* up = (const __half2*)&u;
#pragma unroll
        for (int j = 0; j < 4; j++) {
            float2 p = __half22float2(up[j]);
            acc[2 * j]     += w * p.x;
            acc[2 * j + 1] += w * p.y;
        }
    }
    float inv = 1.0f / (float)(deg + 1);
    size_t no = (size_t)n * DD + lane * 8;
    int c0 = lane * 8;

    uint4 yv = *(const uint4*)&g_Y[(size_t)n * NCOL + BB * DD + c0];
    const __half2* yp = (const __half2*)&yv;
    float4 xv0 = *(const float4*)&xin[no];
    float4 xv1 = *(const float4*)&xin[no + 4];
    float4 bv0 = *(const float4*)&bias[c0];
    float4 bv1 = *(const float4*)&bias[c0 + 4];

    float val[8];
    {
        float2 y0 = __half22float2(yp[0]), y1 = __half22float2(yp[1]);
        float2 y2 = __half22float2(yp[2]), y3 = __half22float2(yp[3]);
        val[0] = acc[0] * inv + y0.x + bv0.x + xv0.x;
        val[1] = acc[1] * inv + y0.y + bv0.y + xv0.y;
        val[2] = acc[2] * inv + y1.x + bv0.z + xv0.z;
        val[3] = acc[3] * inv + y1.y + bv0.w + xv0.w;
        val[4] = acc[4] * inv + y2.x + bv1.x + xv1.x;
        val[5] = acc[5] * inv + y2.y + bv1.y + xv1.y;
        val[6] = acc[6] * inv + y3.x + bv1.z + xv1.z;
        val[7] = acc[7] * inv + y3.y + bv1.w + xv1.w;
    }
    float s = 0.f;
#pragma unroll
    for (int j = 0; j < 8; j++) s += val[j];
#pragma unroll
    for (int k = 16; k > 0; k >>= 1) s += __shfl_xor_sync(0xffffffffu, s, k);
    float mu = s * (1.0f / DD);
    float s2 = 0.f;
#pragma unroll
    for (int j = 0; j < 8; j++) { float d = val[j] - mu; s2 += d * d; }
#pragma unroll
    for (int k = 16; k > 0; k >>= 1) s2 += __shfl_xor_sync(0xffffffffu, s2, k);
    float rstd = rsqrtf(s2 * (1.0f / DD) + LN_EPS);

    float4 gv0 = *(const float4*)&gln[c0];
    float4 gv1 = *(const float4*)&gln[c0 + 4];
    float4 lb0 = *(const float4*)&bln[c0];
    float4 lb1 = *(const float4*)&bln[c0 + 4];
    float y[8];
    y[0] = fmaxf((val[0] - mu) * rstd * gv0.x + lb0.x, 0.f);
    y[1] = fmaxf((val[1] - mu) * rstd * gv0.y + lb0.y, 0.f);
    y[2] = fmaxf((val[2] - mu) * rstd * gv0.z + lb0.z, 0.f);
    y[3] = fmaxf((val[3] - mu) * rstd * gv0.w + lb0.w, 0.f);
    y[4] = fmaxf((val[4] - mu) * rstd * gv1.x + lb1.x, 0.f);
    y[5] = fmaxf((val[5] - mu) * rstd * gv1.y + lb1.y, 0.f);
    y[6] = fmaxf((val[6] - mu) * rstd * gv1.z + lb1.z, 0.f);
    y[7] = fmaxf((val[7] - mu) * rstd * gv1.w + lb1.w, 0.f);

    *(float4*)&out[no]     = make_float4(y[0], y[1], y[2], y[3]);
    *(float4*)&out[no + 4] = make_float4(y[4], y[5], y[6], y[7]);
    if (emit_split) {
        uint4 hv;
        __half2* hp = (__half2*)&hv;
        hp[0] = __floats2half2_rn(y[0], y[1]);
        hp[1] = __floats2half2_rn(y[2], y[3]);
        hp[2] = __floats2half2_rn(y[4], y[5]);
        hp[3] = __floats2half2_rn(y[6], y[7]);
        *(uint4*)&g_Ap[(size_t)n * KK + c0] = hv;
    }
}

// ===========================================================================
static void run_layer(const float* x, const float* att,
                      const float* bias, const float* lg, const float* lb,
                      const __half* Bp, float* out, int M, int emit_split) {
    {
        dim3 grid(NCOL / 128, (M + 127) / 128);   // (18, 391)
        k_gemm_mma<<<grid, 256, 4 * TILE_B>>>(M, Bp);
    }
    k_expand<<<(M + 7) / 8, 256>>>(att, M);
    k_gather_fin<<<(M + 7) / 8, 256>>>(x, bias, lg, lb, out, M, emit_split);
}

extern "C" void kernel_launch(void* const* d_in, const int* in_sizes, int n_in,
                              void* d_out, int out_size) {
    const float* x   = (const float*)d_in[0];
    const int*   ei  = (const int*)d_in[1];
    const int*   et  = (const int*)d_in[2];
    const float* ea  = (const float*)d_in[3];
    const float* basis1 = (const float*)d_in[4];
    const float* att1   = (const float*)d_in[5];
    const float* root1  = (const float*)d_in[6];
    const float* bias1  = (const float*)d_in[7];
    const float* ln1g   = (const float*)d_in[8];
    const float* ln1b   = (const float*)d_in[9];
    const float* basis2 = (const float*)d_in[10];
    const float* att2   = (const float*)d_in[11];
    const float* root2  = (const float*)d_in[12];
    const float* bias2  = (const float*)d_in[13];
    const float* ln2g   = (const float*)d_in[14];
    const float* ln2b   = (const float*)d_in[15];
    float* out = (float*)d_out;

    int M = in_sizes[0] / DD;     // 50000
    int E = in_sizes[2];          // 800000

    cudaFuncSetAttribute(k_gemm_mma, cudaFuncAttributeMaxDynamicSharedMemorySize,
                         4 * TILE_B);

    void* p = nullptr;
    cudaGetSymbolAddress(&p, g_x1);
    float* x1_dev = (float*)p;
    cudaGetSymbolAddress(&p, g_Bp1);
    __half* bp1_dev = (__half*)p;
    cudaGetSymbolAddress(&p, g_Bp2);
    __half* bp2_dev = (__half*)p;

    // Prep both layers' weights + input conversion upfront
    k_prepw<<<NCOL, 256>>>(basis1, root1, bp1_dev);
    k_prepw<<<NCOL, 256>>>(basis2, root2, bp2_dev);
    k_cvt_x<<<(M * DD + 255) / 256, 256>>>(x, M);

    // CSR over dst + used-pair bitmap (shared by both layers)
    int nb = (M + 255) / 256;                  // 196
    k_zero_degfill<<<nb, 256>>>(M);
    k_deg_count<<<(E + 255) / 256, 256>>>(ei, E);
    k_scan1<<<nb, 256>>>(M);
    k_scan2<<<1, 256>>>(nb);
    k_scan3<<<nb, 256>>>(M);
    k_fill<<<(E + 255) / 256, 256>>>(ei, et, ea, E);

    // layer 1
    run_layer(x, att1, bias1, ln1g, ln1b, bp1_dev, x1_dev, M, 1);
    // layer 2 (g_Ap emitted by layer-1 gather_fin)
    run_layer(x1_dev, att2, bias2, ln2g, ln2b, bp2_dev, out, M, 0);
}